// round 1
// baseline (speedup 1.0000x reference)
#include <cuda_runtime.h>
#include <math.h>
#include <stdint.h>

// Problem constants
#define B_   4096
#define E_   16384
#define DIM_ 4096

// GEMM tiling
#define BM 128
#define BN 128
#define BK 16
#define TM 8
#define TN 8
#define NTHREADS 256

// ---------------- device scratch (no allocations allowed) ----------------
__device__ float              g_xnorm[B_];
__device__ float              g_enorm[E_];
__device__ unsigned long long g_best[B_];          // (ordered dist bits << 32) | col
__device__ int                g_counts[E_];
__device__ double             g_loss_partial[B_];

// float -> monotonically ordered uint (total order matching <)
__device__ __forceinline__ unsigned int f2ord(float f) {
    unsigned int u = __float_as_uint(f);
    return (u & 0x80000000u) ? ~u : (u | 0x80000000u);
}

// deterministic in-block double reduction (fixed tree order)
__device__ double block_reduce256(double v) {
    __shared__ double sm[NTHREADS];
    int t = threadIdx.x;
    __syncthreads();               // protect smem reuse across calls
    sm[t] = v;
    __syncthreads();
    #pragma unroll
    for (int s = NTHREADS / 2; s > 0; s >>= 1) {
        if (t < s) sm[t] += sm[t + s];
        __syncthreads();
    }
    return sm[0];
}

// ---------------- init ----------------
__global__ void vq_init() {
    int t = blockIdx.x * blockDim.x + threadIdx.x;
    if (t < B_) g_best[t] = ~0ull;
    if (t < E_) g_counts[t] = 0;
}

// ---------------- row squared norms ----------------
__global__ void vq_rownorm(const float* __restrict__ A, float* __restrict__ out) {
    int r = blockIdx.x;
    const float* p = A + (size_t)r * DIM_;
    double s = 0.0;
    for (int k = threadIdx.x; k < DIM_; k += blockDim.x) {
        float v = p[k];
        s += (double)v * (double)v;
    }
    double tot = block_reduce256(s);
    if (threadIdx.x == 0) out[r] = (float)tot;
}

// ---------------- fused fp32 GEMM + row argmin ----------------
// scores s = x_b . e_n ; dist = fl(fl(xnorm + enorm) - 2*s) ; per-row min+index
__global__ void __launch_bounds__(NTHREADS)
vq_gemm_argmin(const float* __restrict__ X, const float* __restrict__ W) {
    __shared__ float As[BK][BM + 4];
    __shared__ float Bs[BK][BN + 4];
    __shared__ unsigned long long rowbest[BM];

    const int tid = threadIdx.x;
    const int m0 = blockIdx.x * BM;   // x = M tile (A stays hot in L2)
    const int n0 = blockIdx.y * BN;
    const int ty = tid / 16;
    const int tx = tid % 16;

    float acc[TM][TN];
    #pragma unroll
    for (int i = 0; i < TM; ++i)
        #pragma unroll
        for (int j = 0; j < TN; ++j) acc[i][j] = 0.0f;

    for (int k0 = 0; k0 < DIM_; k0 += BK) {
        // load A tile (128 rows x 16 k) and B tile; 512 float4 each, 2 per thread
        #pragma unroll
        for (int j = 0; j < 2; ++j) {
            int idx = tid * 2 + j;          // 0..511
            int row = idx >> 2;             // 0..127
            int k4  = (idx & 3) * 4;        // 0,4,8,12
            float4 va = *(const float4*)(X + (size_t)(m0 + row) * DIM_ + k0 + k4);
            As[k4 + 0][row] = va.x; As[k4 + 1][row] = va.y;
            As[k4 + 2][row] = va.z; As[k4 + 3][row] = va.w;
            float4 vb = *(const float4*)(W + (size_t)(n0 + row) * DIM_ + k0 + k4);
            Bs[k4 + 0][row] = vb.x; Bs[k4 + 1][row] = vb.y;
            Bs[k4 + 2][row] = vb.z; Bs[k4 + 3][row] = vb.w;
        }
        __syncthreads();

        #pragma unroll
        for (int k = 0; k < BK; ++k) {
            float a[TM], b[TN];
            #pragma unroll
            for (int i = 0; i < TM; ++i) a[i] = As[k][ty * TM + i];
            #pragma unroll
            for (int j = 0; j < TN; ++j) b[j] = Bs[k][tx * TN + j];
            #pragma unroll
            for (int i = 0; i < TM; ++i)
                #pragma unroll
                for (int j = 0; j < TN; ++j)
                    acc[i][j] = fmaf(a[i], b[j], acc[i][j]);
        }
        __syncthreads();
    }

    // epilogue: per-row min of fl((xnorm+enorm) - 2s), tie -> lowest index
    for (int i = tid; i < BM; i += NTHREADS) rowbest[i] = ~0ull;
    __syncthreads();

    float en[TN];
    #pragma unroll
    for (int j = 0; j < TN; ++j) en[j] = g_enorm[n0 + tx * TN + j];

    #pragma unroll
    for (int i = 0; i < TM; ++i) {
        int r = ty * TM + i;
        float xn = g_xnorm[m0 + r];
        unsigned long long best = ~0ull;
        #pragma unroll
        for (int j = 0; j < TN; ++j) {
            float t = __fadd_rn(xn, en[j]);                     // fl(||x||^2 + ||e||^2)
            float d = __fadd_rn(t, -2.0f * acc[i][j]);          // fl(t - 2s)
            unsigned long long key =
                ((unsigned long long)f2ord(d) << 32) | (unsigned)(n0 + tx * TN + j);
            best = (key < best) ? key : best;
        }
        atomicMin(&rowbest[r], best);
    }
    __syncthreads();
    for (int i = tid; i < BM; i += NTHREADS)
        atomicMin(&g_best[m0 + i], rowbest[i]);
}

// ---------------- histogram of selected indices ----------------
__global__ void vq_counts() {
    int b = blockIdx.x * blockDim.x + threadIdx.x;
    if (b < B_) {
        int idx = (int)(g_best[b] & 0xffffffffu);
        atomicAdd(&g_counts[idx], 1);
    }
}

// ---------------- quantized output (straight-through) + loss partials ----------------
__global__ void vq_quant(const float* __restrict__ X, const float* __restrict__ W,
                         float* __restrict__ qout) {
    int b = blockIdx.x;
    int idx = (int)(g_best[b] & 0xffffffffu);
    const float4* xr = (const float4*)(X + (size_t)b * DIM_);
    const float4* qr = (const float4*)(W + (size_t)idx * DIM_);
    float* o = qout + (size_t)b * DIM_;   // only 4B-aligned (offset +1 in d_out)
    double s = 0.0;
    for (int c = threadIdx.x; c < DIM_ / 4; c += blockDim.x) {
        float4 x = xr[c];
        float4 q = qr[c];
        float d0 = __fadd_rn(q.x, -x.x);
        float d1 = __fadd_rn(q.y, -x.y);
        float d2 = __fadd_rn(q.z, -x.z);
        float d3 = __fadd_rn(q.w, -x.w);
        o[4 * c + 0] = __fadd_rn(x.x, d0);   // x + (q - x), as in reference STE
        o[4 * c + 1] = __fadd_rn(x.y, d1);
        o[4 * c + 2] = __fadd_rn(x.z, d2);
        o[4 * c + 3] = __fadd_rn(x.w, d3);
        s += (double)d0 * d0 + (double)d1 * d1 + (double)d2 * d2 + (double)d3 * d3;
    }
    double tot = block_reduce256(s);
    if (threadIdx.x == 0) g_loss_partial[b] = tot;
}

// ---------------- one-hot encodings [B, E] ----------------
__global__ void vq_encodings(float* __restrict__ enc) {   // 8B-aligned base
    long long gid = (long long)blockIdx.x * blockDim.x + threadIdx.x;
    const long long total = (long long)B_ * (E_ / 2);
    if (gid >= total) return;
    int b  = (int)(gid >> 13);      // E_/2 = 8192 float2 per row
    int c2 = (int)(gid & 8191);
    int idx = (int)(g_best[b] & 0xffffffffu);
    int c = c2 * 2;
    float2 v;
    v.x = (c == idx) ? 1.0f : 0.0f;
    v.y = (c + 1 == idx) ? 1.0f : 0.0f;
    ((float2*)enc)[gid] = v;
}

// ---------------- finalize: loss scalar + perplexity ----------------
__global__ void vq_finalize(float* __restrict__ out_loss, float* __restrict__ out_perp) {
    int t = threadIdx.x;
    double s = 0.0;
    for (int i = t; i < B_; i += NTHREADS) s += g_loss_partial[i];
    double tot = block_reduce256(s);

    double h = 0.0;
    for (int e = t; e < E_; e += NTHREADS) {
        float p = (float)g_counts[e] * (1.0f / (float)B_);
        float term = p * logf(p + 1e-10f);
        h -= (double)term;
    }
    double H = block_reduce256(h);

    if (t == 0) {
        double m = tot / ((double)B_ * (double)DIM_);
        float mf = (float)m;
        out_loss[0] = __fadd_rn(mf, 0.25f * mf);   // q_latent + 0.25*e_latent
        out_perp[0] = expf((float)H);
    }
}

// ---------------- launch ----------------
extern "C" void kernel_launch(void* const* d_in, const int* in_sizes, int n_in,
                              void* d_out, int out_size) {
    const float* X;
    const float* W;
    if (in_sizes[0] == B_ * DIM_) {
        X = (const float*)d_in[0];
        W = (const float*)d_in[1];
    } else {
        X = (const float*)d_in[1];
        W = (const float*)d_in[0];
    }

    float* out = (float*)d_out;
    // output layout: [loss(1)] [quantized(B*DIM)] [perplexity(1)] [encodings(B*E)]
    float* out_loss = out;
    float* out_q    = out + 1;
    float* out_perp = out + 1 + (size_t)B_ * DIM_;
    float* out_enc  = out + 2 + (size_t)B_ * DIM_;

    float* xnorm;  cudaGetSymbolAddress((void**)&xnorm, g_xnorm);
    float* enorm;  cudaGetSymbolAddress((void**)&enorm, g_enorm);

    vq_init<<<E_ / NTHREADS, NTHREADS>>>();
    vq_rownorm<<<B_, NTHREADS>>>(X, xnorm);
    vq_rownorm<<<E_, NTHREADS>>>(W, enorm);

    dim3 grid(B_ / BM, E_ / BN);   // x = M tile (keeps A resident in L2)
    vq_gemm_argmin<<<grid, NTHREADS>>>(X, W);

    vq_counts<<<B_ / NTHREADS, NTHREADS>>>();
    vq_quant<<<B_, NTHREADS>>>(X, W, out_q);

    long long enc_threads = (long long)B_ * (E_ / 2);
    vq_encodings<<<(unsigned)((enc_threads + NTHREADS - 1) / NTHREADS), NTHREADS>>>(out_enc);

    vq_finalize<<<1, NTHREADS>>>(out_loss, out_perp);
}

// round 4
// speedup vs baseline: 3.0516x; 3.0516x over previous
#include <cuda_runtime.h>
#include <cuda_bf16.h>
#include <math.h>
#include <stdint.h>

// Problem constants
#define B_   4096
#define E_   16384
#define DIM_ 4096
#define NTHREADS 256

// GEMM tiling
#define TILE_M 128
#define TILE_N 128
#define KCHUNK 64                // bf16 elems per K chunk = 128 bytes per row
#define NCHUNKS (DIM_ / KCHUNK)  // 64
#define NSTAGES 3

// dynamic smem layout
#define SOFF_EN   0              // 128 floats enorm
#define SOFF_XN   512            // 128 floats xnorm
#define SOFF_RB   1024           // 128 u64 rowbest
#define SOFF_STAGE 2048
#define STAGE_BYTES 65536        // Ahi 16K | Alo 16K | Bhi 16K | Blo 16K
#define SMEM_TOTAL (SOFF_STAGE + NSTAGES * STAGE_BYTES)  // 198656

// ---------------- device scratch ----------------
__device__ unsigned short     g_Xhi[B_ * DIM_];
__device__ unsigned short     g_Xlo[B_ * DIM_];
__device__ unsigned short     g_Whi[E_ * DIM_];
__device__ unsigned short     g_Wlo[E_ * DIM_];
__device__ float              g_xnorm[B_];
__device__ float              g_enorm[E_];
__device__ unsigned long long g_best[B_];
__device__ int                g_counts[E_];
__device__ double             g_loss_partial[B_];

// ---------------- helpers ----------------
__device__ __forceinline__ uint32_t smem_to_u32(const void* p) {
    uint32_t a;
    asm("{ .reg .u64 t; cvta.to.shared.u64 t, %1; cvt.u32.u64 %0, t; }" : "=r"(a) : "l"(p));
    return a;
}

__device__ __forceinline__ void ldsm4(uint32_t* r, uint32_t addr) {
    asm volatile("ldmatrix.sync.aligned.m8n8.x4.shared.b16 {%0,%1,%2,%3}, [%4];"
        : "=r"(r[0]), "=r"(r[1]), "=r"(r[2]), "=r"(r[3]) : "r"(addr));
}

__device__ __forceinline__ void mma_bf16(float* d, const uint32_t* a, const uint32_t* b) {
    asm volatile(
        "mma.sync.aligned.m16n8k16.row.col.f32.bf16.bf16.f32 "
        "{%0,%1,%2,%3}, {%4,%5,%6,%7}, {%8,%9}, {%0,%1,%2,%3};"
        : "+f"(d[0]), "+f"(d[1]), "+f"(d[2]), "+f"(d[3])
        : "r"(a[0]), "r"(a[1]), "r"(a[2]), "r"(a[3]), "r"(b[0]), "r"(b[1]));
}

__device__ __forceinline__ unsigned int f2ord(float f) {
    unsigned int u = __float_as_uint(f);
    return (u & 0x80000000u) ? ~u : (u | 0x80000000u);
}

__device__ double block_reduce256(double v) {
    __shared__ double sm[NTHREADS];
    int t = threadIdx.x;
    __syncthreads();
    sm[t] = v;
    __syncthreads();
    #pragma unroll
    for (int s = NTHREADS / 2; s > 0; s >>= 1) {
        if (t < s) sm[t] += sm[t + s];
        __syncthreads();
    }
    return sm[0];
}

// ---------------- init ----------------
__global__ void vq_init() {
    int t = blockIdx.x * blockDim.x + threadIdx.x;
    if (t < B_) g_best[t] = ~0ull;
    if (t < E_) g_counts[t] = 0;
}

// ---------------- row squared norms ----------------
__global__ void vq_rownorm(const float* __restrict__ A, float* __restrict__ out) {
    int r = blockIdx.x;
    const float* p = A + (size_t)r * DIM_;
    double s = 0.0;
    for (int k = threadIdx.x; k < DIM_; k += blockDim.x) {
        float v = p[k];
        s += (double)v * (double)v;
    }
    double tot = block_reduce256(s);
    if (threadIdx.x == 0) out[r] = (float)tot;
}

// ---------------- bf16 hi/lo split ----------------
__global__ void vq_split(const float* __restrict__ src,
                         unsigned short* __restrict__ hi,
                         unsigned short* __restrict__ lo, int n4) {
    int i = blockIdx.x * blockDim.x + threadIdx.x;
    if (i >= n4) return;
    float4 v = ((const float4*)src)[i];
    __nv_bfloat16 h0 = __float2bfloat16(v.x);
    __nv_bfloat16 h1 = __float2bfloat16(v.y);
    __nv_bfloat16 h2 = __float2bfloat16(v.z);
    __nv_bfloat16 h3 = __float2bfloat16(v.w);
    __nv_bfloat16 l0 = __float2bfloat16(v.x - __bfloat162float(h0));
    __nv_bfloat16 l1 = __float2bfloat16(v.y - __bfloat162float(h1));
    __nv_bfloat16 l2 = __float2bfloat16(v.z - __bfloat162float(h2));
    __nv_bfloat16 l3 = __float2bfloat16(v.w - __bfloat162float(h3));
    uint2 hp, lp;
    hp.x = (uint32_t)__bfloat16_as_ushort(h0) | ((uint32_t)__bfloat16_as_ushort(h1) << 16);
    hp.y = (uint32_t)__bfloat16_as_ushort(h2) | ((uint32_t)__bfloat16_as_ushort(h3) << 16);
    lp.x = (uint32_t)__bfloat16_as_ushort(l0) | ((uint32_t)__bfloat16_as_ushort(l1) << 16);
    lp.y = (uint32_t)__bfloat16_as_ushort(l2) | ((uint32_t)__bfloat16_as_ushort(l3) << 16);
    ((uint2*)hi)[i] = hp;
    ((uint2*)lo)[i] = lp;
}

// ---------------- HMMA GEMM (split X, split W; 3 passes) + fused argmin ----------------
__global__ void __launch_bounds__(NTHREADS, 1)
vq_gemm_mma(const unsigned short* __restrict__ Xhi, const unsigned short* __restrict__ Xlo,
            const unsigned short* __restrict__ Whi, const unsigned short* __restrict__ Wlo) {
    extern __shared__ char smem[];
    uint32_t sbase = smem_to_u32(smem);
    float* sEn = (float*)(smem + SOFF_EN);
    float* sXn = (float*)(smem + SOFF_XN);
    unsigned long long* rowbest = (unsigned long long*)(smem + SOFF_RB);

    const int tid  = threadIdx.x;
    const int lane = tid & 31;
    const int wid  = tid >> 5;
    const int m0 = blockIdx.x * TILE_M;
    const int n0 = blockIdx.y * TILE_N;
    const int wm = (wid >> 2) * 64;      // warp m offset: 0 / 64
    const int wn = (wid & 3) * 32;       // warp n offset: 0/32/64/96

    if (tid < 128) {
        sEn[tid] = g_enorm[n0 + tid];
        sXn[tid] = g_xnorm[m0 + tid];
        rowbest[tid] = ~0ull;
    }

    // cp.async one K chunk (Ahi, Alo, Bhi, Blo) into stage c%3
    auto load_chunk = [&](int c) {
        int st = c % NSTAGES;
        int k0 = c * KCHUNK;
        uint32_t stage = sbase + SOFF_STAGE + st * STAGE_BYTES;
        #pragma unroll
        for (int i = 0; i < 16; ++i) {
            int id = i * NTHREADS + tid;       // 0..4095
            int tile = id >> 10;               // 0..3
            int q   = id & 1023;
            int row = q >> 3;                  // 0..127
            int c16 = q & 7;
            uint32_t off = (uint32_t)(row * 128 + c16 * 16);
            off ^= ((off >> 3) & 0x70);        // SW128 swizzle
            const unsigned short* g;
            if (tile == 0)      g = Xhi + (size_t)(m0 + row) * DIM_ + k0 + c16 * 8;
            else if (tile == 1) g = Xlo + (size_t)(m0 + row) * DIM_ + k0 + c16 * 8;
            else if (tile == 2) g = Whi + (size_t)(n0 + row) * DIM_ + k0 + c16 * 8;
            else                g = Wlo + (size_t)(n0 + row) * DIM_ + k0 + c16 * 8;
            uint32_t sd = stage + tile * 16384 + off;
            asm volatile("cp.async.cg.shared.global [%0], [%1], 16;" :: "r"(sd), "l"(g) : "memory");
        }
        asm volatile("cp.async.commit_group;" ::: "memory");
    };

    load_chunk(0);
    load_chunk(1);

    float acc[4][4][4];
    #pragma unroll
    for (int i = 0; i < 4; ++i)
        #pragma unroll
        for (int j = 0; j < 4; ++j)
            #pragma unroll
            for (int r = 0; r < 4; ++r) acc[i][j][r] = 0.0f;

    // ldmatrix lane addressing constants
    const int aRow  = lane & 15;
    const int aKoff = (lane >> 4) * 16;                  // k-half byte offset
    const int bRow  = ((lane >> 4) << 3) + (lane & 7);
    const int bKoff = ((lane >> 3) & 1) * 16;

    for (int c = 0; c < NCHUNKS; ++c) {
        asm volatile("cp.async.wait_group 1;" ::: "memory");
        __syncthreads();
        int st = c % NSTAGES;
        uint32_t stg = sbase + SOFF_STAGE + st * STAGE_BYTES;

        #pragma unroll
        for (int s = 0; s < 4; ++s) {
            uint32_t ahi[4][4], alo[4][4], bhi[4][2], blo[4][2];
            #pragma unroll
            for (int mi = 0; mi < 4; ++mi) {
                uint32_t off = (uint32_t)((wm + mi * 16 + aRow) * 128 + s * 32 + aKoff);
                off ^= ((off >> 3) & 0x70);
                ldsm4(ahi[mi], stg + off);
                ldsm4(alo[mi], stg + 16384 + off);
            }
            #pragma unroll
            for (int ni2 = 0; ni2 < 2; ++ni2) {
                uint32_t off = (uint32_t)((wn + ni2 * 16 + bRow) * 128 + s * 32 + bKoff);
                off ^= ((off >> 3) & 0x70);
                uint32_t t[4];
                ldsm4(t, stg + 32768 + off);
                bhi[2 * ni2][0] = t[0]; bhi[2 * ni2][1] = t[1];
                bhi[2 * ni2 + 1][0] = t[2]; bhi[2 * ni2 + 1][1] = t[3];
                ldsm4(t, stg + 49152 + off);
                blo[2 * ni2][0] = t[0]; blo[2 * ni2][1] = t[1];
                blo[2 * ni2 + 1][0] = t[2]; blo[2 * ni2 + 1][1] = t[3];
            }
            #pragma unroll
            for (int mi = 0; mi < 4; ++mi)
                #pragma unroll
                for (int ni = 0; ni < 4; ++ni) {
                    mma_bf16(acc[mi][ni], ahi[mi], bhi[ni]);
                    mma_bf16(acc[mi][ni], alo[mi], bhi[ni]);
                    mma_bf16(acc[mi][ni], ahi[mi], blo[ni]);
                }
        }

        if (c + 2 < NCHUNKS) load_chunk(c + 2);
        else asm volatile("cp.async.commit_group;" ::: "memory");
    }
    __syncthreads();

    // epilogue: fragment -> distance keys -> argmin
    const int gr  = lane >> 2;          // group row 0..7
    const int gc2 = (lane & 3) * 2;
    #pragma unroll
    for (int mi = 0; mi < 4; ++mi) {
        int r0l = wm + mi * 16 + gr;
        int r1l = r0l + 8;
        float xn0 = sXn[r0l];
        float xn1 = sXn[r1l];
        unsigned long long b0 = ~0ull, b1 = ~0ull;
        #pragma unroll
        for (int ni = 0; ni < 4; ++ni)
            #pragma unroll
            for (int j = 0; j < 2; ++j) {
                int nloc = wn + ni * 8 + gc2 + j;
                float en = sEn[nloc];
                unsigned col = (unsigned)(n0 + nloc);
                float d0 = __fadd_rn(__fadd_rn(xn0, en), __fmul_rn(-2.0f, acc[mi][ni][j]));
                float d1 = __fadd_rn(__fadd_rn(xn1, en), __fmul_rn(-2.0f, acc[mi][ni][2 + j]));
                unsigned long long k0 = ((unsigned long long)f2ord(d0) << 32) | col;
                unsigned long long k1 = ((unsigned long long)f2ord(d1) << 32) | col;
                if (k0 < b0) b0 = k0;
                if (k1 < b1) b1 = k1;
            }
        atomicMin(&rowbest[r0l], b0);
        atomicMin(&rowbest[r1l], b1);
    }
    __syncthreads();
    if (tid < 128) atomicMin(&g_best[m0 + tid], rowbest[tid]);
}

// ---------------- histogram ----------------
__global__ void vq_counts() {
    int b = blockIdx.x * blockDim.x + threadIdx.x;
    if (b < B_) {
        int idx = (int)(g_best[b] & 0xffffffffu);
        atomicAdd(&g_counts[idx], 1);
    }
}

// ---------------- quantized output (STE) + loss partials ----------------
__global__ void vq_quant(const float* __restrict__ X, const float* __restrict__ W,
                         float* __restrict__ qout) {
    int b = blockIdx.x;
    int idx = (int)(g_best[b] & 0xffffffffu);
    const float4* xr = (const float4*)(X + (size_t)b * DIM_);
    const float4* qr = (const float4*)(W + (size_t)idx * DIM_);
    float* o = qout + (size_t)b * DIM_;
    double s = 0.0;
    for (int c = threadIdx.x; c < DIM_ / 4; c += blockDim.x) {
        float4 x = xr[c];
        float4 q = qr[c];
        float d0 = __fadd_rn(q.x, -x.x);
        float d1 = __fadd_rn(q.y, -x.y);
        float d2 = __fadd_rn(q.z, -x.z);
        float d3 = __fadd_rn(q.w, -x.w);
        o[4 * c + 0] = __fadd_rn(x.x, d0);
        o[4 * c + 1] = __fadd_rn(x.y, d1);
        o[4 * c + 2] = __fadd_rn(x.z, d2);
        o[4 * c + 3] = __fadd_rn(x.w, d3);
        s += (double)d0 * d0 + (double)d1 * d1 + (double)d2 * d2 + (double)d3 * d3;
    }
    double tot = block_reduce256(s);
    if (threadIdx.x == 0) g_loss_partial[b] = tot;
}

// ---------------- one-hot encodings ----------------
__global__ void vq_encodings(float* __restrict__ enc) {
    long long gid = (long long)blockIdx.x * blockDim.x + threadIdx.x;
    const long long total = (long long)B_ * (E_ / 2);
    if (gid >= total) return;
    int b  = (int)(gid >> 13);
    int c2 = (int)(gid & 8191);
    int idx = (int)(g_best[b] & 0xffffffffu);
    int c = c2 * 2;
    float2 v;
    v.x = (c == idx) ? 1.0f : 0.0f;
    v.y = (c + 1 == idx) ? 1.0f : 0.0f;
    ((float2*)enc)[gid] = v;
}

// ---------------- finalize ----------------
__global__ void vq_finalize(float* __restrict__ out_loss, float* __restrict__ out_perp) {
    int t = threadIdx.x;
    double s = 0.0;
    for (int i = t; i < B_; i += NTHREADS) s += g_loss_partial[i];
    double tot = block_reduce256(s);

    double h = 0.0;
    for (int e = t; e < E_; e += NTHREADS) {
        float p = (float)g_counts[e] * (1.0f / (float)B_);
        float term = p * logf(p + 1e-10f);
        h -= (double)term;
    }
    double H = block_reduce256(h);

    if (t == 0) {
        double m = tot / ((double)B_ * (double)DIM_);
        float mf = (float)m;
        out_loss[0] = __fadd_rn(mf, 0.25f * mf);
        out_perp[0] = expf((float)H);
    }
}

// ---------------- launch ----------------
extern "C" void kernel_launch(void* const* d_in, const int* in_sizes, int n_in,
                              void* d_out, int out_size) {
    const float* X;
    const float* W;
    if (in_sizes[0] == B_ * DIM_) {
        X = (const float*)d_in[0];
        W = (const float*)d_in[1];
    } else {
        X = (const float*)d_in[1];
        W = (const float*)d_in[0];
    }

    float* out = (float*)d_out;
    float* out_loss = out;
    float* out_q    = out + 1;
    float* out_perp = out + 1 + (size_t)B_ * DIM_;
    float* out_enc  = out + 2 + (size_t)B_ * DIM_;

    float* xnorm;  cudaGetSymbolAddress((void**)&xnorm, g_xnorm);
    float* enorm;  cudaGetSymbolAddress((void**)&enorm, g_enorm);
    unsigned short *xhi, *xlo, *whi, *wlo;
    cudaGetSymbolAddress((void**)&xhi, g_Xhi);
    cudaGetSymbolAddress((void**)&xlo, g_Xlo);
    cudaGetSymbolAddress((void**)&whi, g_Whi);
    cudaGetSymbolAddress((void**)&wlo, g_Wlo);

    vq_init<<<E_ / NTHREADS, NTHREADS>>>();
    vq_rownorm<<<B_, NTHREADS>>>(X, xnorm);
    vq_rownorm<<<E_, NTHREADS>>>(W, enorm);

    int nx4 = B_ * DIM_ / 4;
    int nw4 = E_ * DIM_ / 4;
    vq_split<<<(nx4 + NTHREADS - 1) / NTHREADS, NTHREADS>>>(X, xhi, xlo, nx4);
    vq_split<<<(nw4 + NTHREADS - 1) / NTHREADS, NTHREADS>>>(W, whi, wlo, nw4);

    cudaFuncSetAttribute(vq_gemm_mma, cudaFuncAttributeMaxDynamicSharedMemorySize, SMEM_TOTAL);
    dim3 grid(B_ / TILE_M, E_ / TILE_N);   // x = M fastest: B tiles reused in L2
    vq_gemm_mma<<<grid, NTHREADS, SMEM_TOTAL>>>(xhi, xlo, whi, wlo);

    vq_counts<<<B_ / NTHREADS, NTHREADS>>>();
    vq_quant<<<B_, NTHREADS>>>(X, W, out_q);

    long long enc_threads = (long long)B_ * (E_ / 2);
    vq_encodings<<<(unsigned)((enc_threads + NTHREADS - 1) / NTHREADS), NTHREADS>>>(out_enc);

    vq_finalize<<<1, NTHREADS>>>(out_loss, out_perp);
}

// round 6
// speedup vs baseline: 4.9671x; 1.6277x over previous
#include <cuda_runtime.h>
#include <cuda_bf16.h>
#include <math.h>
#include <stdint.h>

// Problem constants
#define B_   4096
#define E_   16384
#define DIM_ 4096
#define NTHREADS 256

// GEMM tiling
#define TILE_M 128
#define TILE_N 128
#define KCHUNK 64                // bf16 elems per K chunk = 128 bytes per row
#define NCHUNKS (DIM_ / KCHUNK)  // 64
#define NSTAGES 3

#define NGROUPS (E_ / 32)        // 512 groups of 32 cols per row
#define MARGIN_ULPS 3u           // threshold = coarse min + 3 fp32 grid steps
#define MAXCAND 96

// dynamic smem layout (GEMM)
#define SOFF_EN   0              // 128 floats enorm
#define SOFF_XN   512            // 128 floats xnorm
#define SOFF_STAGE 1024
#define STAGE_BYTES 32768        // Xb 16K | Wb 16K
#define SMEM_TOTAL (SOFF_STAGE + NSTAGES * STAGE_BYTES)  // 99328

// ---------------- device scratch ----------------
__device__ unsigned short     g_Xb[B_ * DIM_];
__device__ unsigned short     g_Wb[E_ * DIM_];
__device__ unsigned long long g_top2[(size_t)B_ * NGROUPS * 2];   // 32MB
__device__ float              g_xnorm[B_];
__device__ float              g_enorm[E_];
__device__ unsigned long long g_best[B_];
__device__ int                g_counts[E_];
__device__ double             g_loss_partial[B_];

// ---------------- helpers ----------------
__device__ __forceinline__ uint32_t smem_to_u32(const void* p) {
    uint32_t a;
    asm("{ .reg .u64 t; cvta.to.shared.u64 t, %1; cvt.u32.u64 %0, t; }" : "=r"(a) : "l"(p));
    return a;
}

__device__ __forceinline__ void ldsm4(uint32_t* r, uint32_t addr) {
    asm volatile("ldmatrix.sync.aligned.m8n8.x4.shared.b16 {%0,%1,%2,%3}, [%4];"
        : "=r"(r[0]), "=r"(r[1]), "=r"(r[2]), "=r"(r[3]) : "r"(addr));
}

__device__ __forceinline__ void mma_bf16(float* d, const uint32_t* a, const uint32_t* b) {
    asm volatile(
        "mma.sync.aligned.m16n8k16.row.col.f32.bf16.bf16.f32 "
        "{%0,%1,%2,%3}, {%4,%5,%6,%7}, {%8,%9}, {%0,%1,%2,%3};"
        : "+f"(d[0]), "+f"(d[1]), "+f"(d[2]), "+f"(d[3])
        : "r"(a[0]), "r"(a[1]), "r"(a[2]), "r"(a[3]), "r"(b[0]), "r"(b[1]));
}

__device__ __forceinline__ unsigned int f2ord(float f) {
    unsigned int u = __float_as_uint(f);
    return (u & 0x80000000u) ? ~u : (u | 0x80000000u);
}

__device__ double block_reduce256(double v) {
    __shared__ double sm[NTHREADS];
    int t = threadIdx.x;
    __syncthreads();
    sm[t] = v;
    __syncthreads();
    #pragma unroll
    for (int s = NTHREADS / 2; s > 0; s >>= 1) {
        if (t < s) sm[t] += sm[t + s];
        __syncthreads();
    }
    return sm[0];
}

// ---------------- init ----------------
__global__ void vq_init() {
    int t = blockIdx.x * blockDim.x + threadIdx.x;
    if (t < E_) g_counts[t] = 0;
}

// ---------------- row squared norms ----------------
__global__ void vq_rownorm(const float* __restrict__ A, float* __restrict__ out) {
    int r = blockIdx.x;
    const float* p = A + (size_t)r * DIM_;
    double s = 0.0;
    for (int k = threadIdx.x; k < DIM_; k += blockDim.x) {
        float v = p[k];
        s += (double)v * (double)v;
    }
    double tot = block_reduce256(s);
    if (threadIdx.x == 0) out[r] = (float)tot;
}

// ---------------- fp32 -> bf16 ----------------
__global__ void vq_tobf16(const float* __restrict__ src,
                          unsigned short* __restrict__ dst, int n4) {
    int i = blockIdx.x * blockDim.x + threadIdx.x;
    if (i >= n4) return;
    float4 v = ((const float4*)src)[i];
    uint2 p;
    p.x = (uint32_t)__bfloat16_as_ushort(__float2bfloat16(v.x))
        | ((uint32_t)__bfloat16_as_ushort(__float2bfloat16(v.y)) << 16);
    p.y = (uint32_t)__bfloat16_as_ushort(__float2bfloat16(v.z))
        | ((uint32_t)__bfloat16_as_ushort(__float2bfloat16(v.w)) << 16);
    ((uint2*)dst)[i] = p;
}

// ---------------- coarse HMMA GEMM + per-(row,32col-group) top-2 ----------------
__global__ void __launch_bounds__(NTHREADS, 1)
vq_gemm_mma(const unsigned short* __restrict__ Xb, const unsigned short* __restrict__ Wb) {
    extern __shared__ char smem[];
    uint32_t sbase = smem_to_u32(smem);
    float* sEn = (float*)(smem + SOFF_EN);
    float* sXn = (float*)(smem + SOFF_XN);

    const int tid  = threadIdx.x;
    const int lane = tid & 31;
    const int wid  = tid >> 5;
    const int m0 = blockIdx.x * TILE_M;
    const int n0 = blockIdx.y * TILE_N;
    const int wm = (wid >> 2) * 64;      // warp m offset: 0 / 64
    const int wn = (wid & 3) * 32;       // warp n offset: 0/32/64/96

    if (tid < 128) {
        sEn[tid] = g_enorm[n0 + tid];
        sXn[tid] = g_xnorm[m0 + tid];
    }

    // cp.async one K chunk (Xb, Wb) into stage c%3
    auto load_chunk = [&](int c) {
        int st = c % NSTAGES;
        int k0 = c * KCHUNK;
        uint32_t stage = sbase + SOFF_STAGE + st * STAGE_BYTES;
        #pragma unroll
        for (int i = 0; i < 8; ++i) {
            int id = i * NTHREADS + tid;       // 0..2047
            int tile = id >> 10;               // 0..1
            int q   = id & 1023;
            int row = q >> 3;                  // 0..127
            int c16 = q & 7;
            uint32_t off = (uint32_t)(row * 128 + c16 * 16);
            off ^= ((off >> 3) & 0x70);        // SW128 swizzle
            const unsigned short* g;
            if (tile == 0) g = Xb + (size_t)(m0 + row) * DIM_ + k0 + c16 * 8;
            else           g = Wb + (size_t)(n0 + row) * DIM_ + k0 + c16 * 8;
            uint32_t sd = stage + tile * 16384 + off;
            asm volatile("cp.async.cg.shared.global [%0], [%1], 16;" :: "r"(sd), "l"(g) : "memory");
        }
        asm volatile("cp.async.commit_group;" ::: "memory");
    };

    load_chunk(0);
    load_chunk(1);

    float acc[4][4][4];
    #pragma unroll
    for (int i = 0; i < 4; ++i)
        #pragma unroll
        for (int j = 0; j < 4; ++j)
            #pragma unroll
            for (int r = 0; r < 4; ++r) acc[i][j][r] = 0.0f;

    const int aRow  = lane & 15;
    const int aKoff = (lane >> 4) * 16;
    const int bRow  = ((lane >> 4) << 3) + (lane & 7);
    const int bKoff = ((lane >> 3) & 1) * 16;

    for (int c = 0; c < NCHUNKS; ++c) {
        asm volatile("cp.async.wait_group 1;" ::: "memory");
        __syncthreads();
        int st = c % NSTAGES;
        uint32_t stg = sbase + SOFF_STAGE + st * STAGE_BYTES;

        #pragma unroll
        for (int s = 0; s < 4; ++s) {
            uint32_t af[4][4], bf[4][2];
            #pragma unroll
            for (int mi = 0; mi < 4; ++mi) {
                uint32_t off = (uint32_t)((wm + mi * 16 + aRow) * 128 + s * 32 + aKoff);
                off ^= ((off >> 3) & 0x70);
                ldsm4(af[mi], stg + off);
            }
            #pragma unroll
            for (int ni2 = 0; ni2 < 2; ++ni2) {
                uint32_t off = (uint32_t)((wn + ni2 * 16 + bRow) * 128 + s * 32 + bKoff);
                off ^= ((off >> 3) & 0x70);
                uint32_t t[4];
                ldsm4(t, stg + 16384 + off);
                bf[2 * ni2][0] = t[0]; bf[2 * ni2][1] = t[1];
                bf[2 * ni2 + 1][0] = t[2]; bf[2 * ni2 + 1][1] = t[3];
            }
            #pragma unroll
            for (int mi = 0; mi < 4; ++mi)
                #pragma unroll
                for (int ni = 0; ni < 4; ++ni)
                    mma_bf16(acc[mi][ni], af[mi], bf[ni]);
        }

        if (c + 2 < NCHUNKS) load_chunk(c + 2);
        else asm volatile("cp.async.commit_group;" ::: "memory");
    }
    __syncthreads();

    // epilogue: per-row top-2 within this warp's 32-col group
    const int gr = lane >> 2;           // row in 8-group
    const int gc = lane & 3;
    const int gc2 = gc * 2;
    const int group = (n0 + wn) >> 5;   // global 32-col group id

    #pragma unroll
    for (int mi = 0; mi < 4; ++mi) {
        #pragma unroll
        for (int half = 0; half < 2; ++half) {
            int rl = wm + mi * 16 + gr + half * 8;
            float xn = sXn[rl];
            unsigned long long k1 = ~0ull, k2 = ~0ull;
            #pragma unroll
            for (int ni = 0; ni < 4; ++ni)
                #pragma unroll
                for (int j = 0; j < 2; ++j) {
                    int nloc = wn + ni * 8 + gc2 + j;
                    float d = __fadd_rn(__fadd_rn(xn, sEn[nloc]),
                                        __fmul_rn(-2.0f, acc[mi][ni][half * 2 + j]));
                    unsigned long long key =
                        ((unsigned long long)f2ord(d) << 32) | (unsigned)(n0 + nloc);
                    if (key < k1) { k2 = k1; k1 = key; }
                    else if (key < k2) { k2 = key; }
                }
            // merge top-2 across the 4 lanes holding this row
            #pragma unroll
            for (int x = 1; x <= 2; x <<= 1) {
                unsigned long long o1 = __shfl_xor_sync(0xffffffffu, k1, x);
                unsigned long long o2 = __shfl_xor_sync(0xffffffffu, k2, x);
                unsigned long long n1 = (k1 < o1) ? k1 : o1;
                unsigned long long mx = (k1 < o1) ? o1 : k1;
                unsigned long long mn2 = (k2 < o2) ? k2 : o2;
                k1 = n1;
                k2 = (mx < mn2) ? mx : mn2;
            }
            if (gc == 0) {
                size_t base = ((size_t)(m0 + rl) * NGROUPS + group) * 2;
                g_top2[base]     = k1;
                g_top2[base + 1] = k2;
            }
        }
    }
}

// ---------------- candidate selection + exact rescore ----------------
__global__ void __launch_bounds__(NTHREADS)
vq_candidates(const float* __restrict__ X, const float* __restrict__ W) {
    __shared__ unsigned long long skey[NTHREADS];
    __shared__ int scand[MAXCAND];
    __shared__ int scnt;
    __shared__ unsigned long long sthr;

    int b = blockIdx.x;
    int t = threadIdx.x;
    const unsigned long long* keys = g_top2 + (size_t)b * NGROUPS * 2;

    // per-thread min over 4 keys, then tree-min
    unsigned long long mk = ~0ull;
    unsigned long long my[4];
    #pragma unroll
    for (int i = 0; i < 4; ++i) {
        my[i] = keys[t + i * NTHREADS];
        if (my[i] < mk) mk = my[i];
    }
    skey[t] = mk;
    __syncthreads();
    #pragma unroll
    for (int s = NTHREADS / 2; s > 0; s >>= 1) {
        if (t < s && skey[t + s] < skey[t]) skey[t] = skey[t + s];
        __syncthreads();
    }
    if (t == 0) {
        scnt = 0;
        // threshold in ordered-uint (grid-step) space: coarse min + MARGIN_ULPS steps
        unsigned int mord = (unsigned int)(skey[0] >> 32);
        sthr = ((unsigned long long)(mord + MARGIN_ULPS) << 32) | 0xffffffffull;
    }
    __syncthreads();

    unsigned long long thr = sthr;
    #pragma unroll
    for (int i = 0; i < 4; ++i) {
        if (my[i] <= thr) {
            int pos = atomicAdd(&scnt, 1);
            if (pos < MAXCAND) scand[pos] = (int)(my[i] & 0xffffffffu);
        }
    }
    __syncthreads();
    int n = scnt < MAXCAND ? scnt : MAXCAND;

    // exact rescore: double-accumulated dot, fp32 distance rounding
    const float* xr = X + (size_t)b * DIM_;
    float xn = g_xnorm[b];
    unsigned long long best = ~0ull;
    for (int i = 0; i < n; ++i) {
        int col = scand[i];
        const float* wr = W + (size_t)col * DIM_;
        double s = 0.0;
        for (int k = t; k < DIM_; k += NTHREADS)
            s += (double)xr[k] * (double)wr[k];
        double tot = block_reduce256(s);
        if (t == 0) {
            float d = __fadd_rn(__fadd_rn(xn, g_enorm[col]), -2.0f * (float)tot);
            unsigned long long key = ((unsigned long long)f2ord(d) << 32) | (unsigned)col;
            if (key < best) best = key;
        }
    }
    if (t == 0) g_best[b] = best;
}

// ---------------- histogram ----------------
__global__ void vq_counts() {
    int b = blockIdx.x * blockDim.x + threadIdx.x;
    if (b < B_) {
        int idx = (int)(g_best[b] & 0xffffffffu);
        atomicAdd(&g_counts[idx], 1);
    }
}

// ---------------- quantized output (STE) + loss partials ----------------
__global__ void vq_quant(const float* __restrict__ X, const float* __restrict__ W,
                         float* __restrict__ qout) {
    int b = blockIdx.x;
    int idx = (int)(g_best[b] & 0xffffffffu);
    const float4* xr = (const float4*)(X + (size_t)b * DIM_);
    const float4* qr = (const float4*)(W + (size_t)idx * DIM_);
    float* o = qout + (size_t)b * DIM_;
    double s = 0.0;
    for (int c = threadIdx.x; c < DIM_ / 4; c += blockDim.x) {
        float4 x = xr[c];
        float4 q = qr[c];
        float d0 = __fadd_rn(q.x, -x.x);
        float d1 = __fadd_rn(q.y, -x.y);
        float d2 = __fadd_rn(q.z, -x.z);
        float d3 = __fadd_rn(q.w, -x.w);
        o[4 * c + 0] = __fadd_rn(x.x, d0);
        o[4 * c + 1] = __fadd_rn(x.y, d1);
        o[4 * c + 2] = __fadd_rn(x.z, d2);
        o[4 * c + 3] = __fadd_rn(x.w, d3);
        s += (double)d0 * d0 + (double)d1 * d1 + (double)d2 * d2 + (double)d3 * d3;
    }
    double tot = block_reduce256(s);
    if (threadIdx.x == 0) g_loss_partial[b] = tot;
}

// ---------------- one-hot encodings ----------------
__global__ void vq_encodings(float* __restrict__ enc) {
    long long gid = (long long)blockIdx.x * blockDim.x + threadIdx.x;
    const long long total = (long long)B_ * (E_ / 2);
    if (gid >= total) return;
    int b  = (int)(gid >> 13);
    int c2 = (int)(gid & 8191);
    int idx = (int)(g_best[b] & 0xffffffffu);
    int c = c2 * 2;
    float2 v;
    v.x = (c == idx) ? 1.0f : 0.0f;
    v.y = (c + 1 == idx) ? 1.0f : 0.0f;
    ((float2*)enc)[gid] = v;
}

// ---------------- finalize ----------------
__global__ void vq_finalize(float* __restrict__ out_loss, float* __restrict__ out_perp) {
    int t = threadIdx.x;
    double s = 0.0;
    for (int i = t; i < B_; i += NTHREADS) s += g_loss_partial[i];
    double tot = block_reduce256(s);

    double h = 0.0;
    for (int e = t; e < E_; e += NTHREADS) {
        float p = (float)g_counts[e] * (1.0f / (float)B_);
        float term = p * logf(p + 1e-10f);
        h -= (double)term;
    }
    double H = block_reduce256(h);

    if (t == 0) {
        double m = tot / ((double)B_ * (double)DIM_);
        float mf = (float)m;
        out_loss[0] = __fadd_rn(mf, 0.25f * mf);
        out_perp[0] = expf((float)H);
    }
}

// ---------------- launch ----------------
extern "C" void kernel_launch(void* const* d_in, const int* in_sizes, int n_in,
                              void* d_out, int out_size) {
    const float* X;
    const float* W;
    if (in_sizes[0] == B_ * DIM_) {
        X = (const float*)d_in[0];
        W = (const float*)d_in[1];
    } else {
        X = (const float*)d_in[1];
        W = (const float*)d_in[0];
    }

    float* out = (float*)d_out;
    float* out_loss = out;
    float* out_q    = out + 1;
    float* out_perp = out + 1 + (size_t)B_ * DIM_;
    float* out_enc  = out + 2 + (size_t)B_ * DIM_;

    float* xnorm;  cudaGetSymbolAddress((void**)&xnorm, g_xnorm);
    float* enorm;  cudaGetSymbolAddress((void**)&enorm, g_enorm);
    unsigned short *xb, *wb;
    cudaGetSymbolAddress((void**)&xb, g_Xb);
    cudaGetSymbolAddress((void**)&wb, g_Wb);

    vq_init<<<E_ / NTHREADS, NTHREADS>>>();
    vq_rownorm<<<B_, NTHREADS>>>(X, xnorm);
    vq_rownorm<<<E_, NTHREADS>>>(W, enorm);

    int nx4 = B_ * DIM_ / 4;
    int nw4 = E_ * DIM_ / 4;
    vq_tobf16<<<(nx4 + NTHREADS - 1) / NTHREADS, NTHREADS>>>(X, xb, nx4);
    vq_tobf16<<<(nw4 + NTHREADS - 1) / NTHREADS, NTHREADS>>>(W, wb, nw4);

    cudaFuncSetAttribute(vq_gemm_mma, cudaFuncAttributeMaxDynamicSharedMemorySize, SMEM_TOTAL);
    dim3 grid(B_ / TILE_M, E_ / TILE_N);   // x = M fastest: B tiles reused in L2
    vq_gemm_mma<<<grid, NTHREADS, SMEM_TOTAL>>>(xb, wb);

    vq_candidates<<<B_, NTHREADS>>>(X, W);

    vq_counts<<<B_ / NTHREADS, NTHREADS>>>();
    vq_quant<<<B_, NTHREADS>>>(X, W, out_q);

    long long enc_threads = (long long)B_ * (E_ / 2);
    vq_encodings<<<(unsigned)((enc_threads + NTHREADS - 1) / NTHREADS), NTHREADS>>>(out_enc);

    vq_finalize<<<1, NTHREADS>>>(out_loss, out_perp);
}

// round 7
// speedup vs baseline: 5.2327x; 1.0535x over previous
#include <cuda_runtime.h>
#include <cuda_bf16.h>
#include <math.h>
#include <stdint.h>

// Problem constants
#define B_   4096
#define E_   16384
#define DIM_ 4096
#define NTHREADS 256

// GEMM tiling
#define TILE_M 128
#define TILE_N 256
#define KCHUNK 64                // bf16 elems per K chunk = 128 bytes per row
#define NCHUNKS (DIM_ / KCHUNK)  // 64
#define NSTAGES 4

#define NGROUPS (E_ / 32)        // 512 groups of 32 cols per row
#define MARGIN_ULPS 3u           // threshold = coarse min + 3 fp32 grid steps
#define MAXCAND 96

// dynamic smem layout (GEMM)
#define SOFF_EN   0              // 256 floats enorm
#define SOFF_XN   1024           // 128 floats xnorm
#define SOFF_STAGE 2048
#define STAGE_BYTES 49152        // Xb 16K | Wb 32K
#define SMEM_TOTAL (SOFF_STAGE + NSTAGES * STAGE_BYTES)  // 198656

// ---------------- device scratch ----------------
__device__ unsigned short     g_Xb[B_ * DIM_];
__device__ unsigned short     g_Wb[E_ * DIM_];
__device__ unsigned long long g_top2[(size_t)B_ * NGROUPS * 2];   // 32MB
__device__ float              g_xnorm[B_];
__device__ float              g_enorm[E_];
__device__ unsigned long long g_best[B_];
__device__ int                g_counts[E_];
__device__ double             g_loss_partial[B_];

// ---------------- helpers ----------------
__device__ __forceinline__ uint32_t smem_to_u32(const void* p) {
    uint32_t a;
    asm("{ .reg .u64 t; cvta.to.shared.u64 t, %1; cvt.u32.u64 %0, t; }" : "=r"(a) : "l"(p));
    return a;
}

__device__ __forceinline__ void ldsm4(uint32_t* r, uint32_t addr) {
    asm volatile("ldmatrix.sync.aligned.m8n8.x4.shared.b16 {%0,%1,%2,%3}, [%4];"
        : "=r"(r[0]), "=r"(r[1]), "=r"(r[2]), "=r"(r[3]) : "r"(addr));
}

__device__ __forceinline__ void mma_bf16(float* d, const uint32_t* a, const uint32_t* b) {
    asm volatile(
        "mma.sync.aligned.m16n8k16.row.col.f32.bf16.bf16.f32 "
        "{%0,%1,%2,%3}, {%4,%5,%6,%7}, {%8,%9}, {%0,%1,%2,%3};"
        : "+f"(d[0]), "+f"(d[1]), "+f"(d[2]), "+f"(d[3])
        : "r"(a[0]), "r"(a[1]), "r"(a[2]), "r"(a[3]), "r"(b[0]), "r"(b[1]));
}

__device__ __forceinline__ unsigned int f2ord(float f) {
    unsigned int u = __float_as_uint(f);
    return (u & 0x80000000u) ? ~u : (u | 0x80000000u);
}

__device__ double block_reduce256(double v) {
    __shared__ double sm[NTHREADS];
    int t = threadIdx.x;
    __syncthreads();
    sm[t] = v;
    __syncthreads();
    #pragma unroll
    for (int s = NTHREADS / 2; s > 0; s >>= 1) {
        if (t < s) sm[t] += sm[t + s];
        __syncthreads();
    }
    return sm[0];
}

// ---------------- init ----------------
__global__ void vq_init() {
    int t = blockIdx.x * blockDim.x + threadIdx.x;
    if (t < E_) g_counts[t] = 0;
}

// ---------------- fused row norm + bf16 convert ----------------
__global__ void vq_prep(const float* __restrict__ src,
                        unsigned short* __restrict__ dst,
                        float* __restrict__ norm) {
    int r = blockIdx.x;
    const float4* p = (const float4*)(src + (size_t)r * DIM_);
    uint2* o = (uint2*)(dst + (size_t)r * DIM_);
    double s = 0.0;
    #pragma unroll
    for (int i = 0; i < DIM_ / 4 / NTHREADS; ++i) {
        int c = threadIdx.x + i * NTHREADS;
        float4 v = p[c];
        s += (double)v.x * v.x + (double)v.y * v.y
           + (double)v.z * v.z + (double)v.w * v.w;
        uint2 q;
        q.x = (uint32_t)__bfloat16_as_ushort(__float2bfloat16(v.x))
            | ((uint32_t)__bfloat16_as_ushort(__float2bfloat16(v.y)) << 16);
        q.y = (uint32_t)__bfloat16_as_ushort(__float2bfloat16(v.z))
            | ((uint32_t)__bfloat16_as_ushort(__float2bfloat16(v.w)) << 16);
        o[c] = q;
    }
    double tot = block_reduce256(s);
    if (threadIdx.x == 0) norm[r] = (float)tot;
}

// ---------------- coarse HMMA GEMM (128x256 tile) + per-(row,32col-group) top-2 ----------------
__global__ void __launch_bounds__(NTHREADS)
vq_gemm_mma(const unsigned short* __restrict__ Xb, const unsigned short* __restrict__ Wb) {
    extern __shared__ char smem[];
    uint32_t sbase = smem_to_u32(smem);
    float* sEn = (float*)(smem + SOFF_EN);
    float* sXn = (float*)(smem + SOFF_XN);

    const int tid  = threadIdx.x;
    const int lane = tid & 31;
    const int wid  = tid >> 5;
    const int m0 = blockIdx.x * TILE_M;
    const int n0 = blockIdx.y * TILE_N;
    const int wm = (wid >> 2) * 64;      // warp m offset: 0 / 64
    const int wn = (wid & 3) * 64;       // warp n offset: 0/64/128/192

    sEn[tid] = g_enorm[n0 + tid];
    if (tid < 128) sXn[tid] = g_xnorm[m0 + tid];

    // cp.async one K chunk (Xb 128 rows, Wb 256 rows) into stage c%4
    auto load_chunk = [&](int c) {
        int st = c & (NSTAGES - 1);
        int k0 = c * KCHUNK;
        uint32_t stage = sbase + SOFF_STAGE + st * STAGE_BYTES;
        #pragma unroll
        for (int i = 0; i < 12; ++i) {
            int id = i * NTHREADS + tid;       // 0..3071
            const unsigned short* g;
            uint32_t sd;
            if (id < 1024) {
                int row = id >> 3, c16 = id & 7;
                uint32_t off = (uint32_t)(row * 128 + c16 * 16);
                off ^= ((off >> 3) & 0x70);
                g = Xb + (size_t)(m0 + row) * DIM_ + k0 + c16 * 8;
                sd = stage + off;
            } else {
                int q = id - 1024;             // 0..2047
                int row = q >> 3, c16 = q & 7;
                uint32_t off = (uint32_t)(row * 128 + c16 * 16);
                off ^= ((off >> 3) & 0x70);
                g = Wb + (size_t)(n0 + row) * DIM_ + k0 + c16 * 8;
                sd = stage + 16384 + off;
            }
            asm volatile("cp.async.cg.shared.global [%0], [%1], 16;" :: "r"(sd), "l"(g) : "memory");
        }
        asm volatile("cp.async.commit_group;" ::: "memory");
    };

    load_chunk(0);
    load_chunk(1);
    load_chunk(2);

    float acc[4][8][4];
    #pragma unroll
    for (int i = 0; i < 4; ++i)
        #pragma unroll
        for (int j = 0; j < 8; ++j)
            #pragma unroll
            for (int r = 0; r < 4; ++r) acc[i][j][r] = 0.0f;

    const int aRow  = lane & 15;
    const int aKoff = (lane >> 4) * 16;
    const int bRow  = ((lane >> 4) << 3) + (lane & 7);
    const int bKoff = ((lane >> 3) & 1) * 16;

    for (int c = 0; c < NCHUNKS; ++c) {
        asm volatile("cp.async.wait_group 2;" ::: "memory");
        __syncthreads();
        int st = c & (NSTAGES - 1);
        uint32_t stg = sbase + SOFF_STAGE + st * STAGE_BYTES;

        #pragma unroll
        for (int s = 0; s < 4; ++s) {
            uint32_t af[4][4], bf[8][2];
            #pragma unroll
            for (int mi = 0; mi < 4; ++mi) {
                uint32_t off = (uint32_t)((wm + mi * 16 + aRow) * 128 + s * 32 + aKoff);
                off ^= ((off >> 3) & 0x70);
                ldsm4(af[mi], stg + off);
            }
            #pragma unroll
            for (int ni2 = 0; ni2 < 4; ++ni2) {
                uint32_t off = (uint32_t)((wn + ni2 * 16 + bRow) * 128 + s * 32 + bKoff);
                off ^= ((off >> 3) & 0x70);
                uint32_t t[4];
                ldsm4(t, stg + 16384 + off);
                bf[2 * ni2][0] = t[0]; bf[2 * ni2][1] = t[1];
                bf[2 * ni2 + 1][0] = t[2]; bf[2 * ni2 + 1][1] = t[3];
            }
            #pragma unroll
            for (int mi = 0; mi < 4; ++mi)
                #pragma unroll
                for (int ni = 0; ni < 8; ++ni)
                    mma_bf16(acc[mi][ni], af[mi], bf[ni]);
        }

        if (c + 3 < NCHUNKS) load_chunk(c + 3);
        else asm volatile("cp.async.commit_group;" ::: "memory");
    }
    __syncthreads();

    // epilogue: per-row top-2 within each of this warp's two 32-col groups
    const int gr = lane >> 2;           // row in 8-group
    const int gc = lane & 3;
    const int gc2 = gc * 2;
    const int group0 = (n0 + wn) >> 5;  // first global 32-col group id

    #pragma unroll
    for (int mi = 0; mi < 4; ++mi) {
        #pragma unroll
        for (int half = 0; half < 2; ++half) {
            int rl = wm + mi * 16 + gr + half * 8;
            float xn = sXn[rl];
            #pragma unroll
            for (int grp = 0; grp < 2; ++grp) {
                unsigned long long k1 = ~0ull, k2 = ~0ull;
                #pragma unroll
                for (int ni = grp * 4; ni < grp * 4 + 4; ++ni)
                    #pragma unroll
                    for (int j = 0; j < 2; ++j) {
                        int nloc = wn + ni * 8 + gc2 + j;
                        float d = __fadd_rn(__fadd_rn(xn, sEn[nloc]),
                                            __fmul_rn(-2.0f, acc[mi][ni][half * 2 + j]));
                        unsigned long long key =
                            ((unsigned long long)f2ord(d) << 32) | (unsigned)(n0 + nloc);
                        if (key < k1) { k2 = k1; k1 = key; }
                        else if (key < k2) { k2 = key; }
                    }
                // merge top-2 across the 4 lanes holding this row
                #pragma unroll
                for (int x = 1; x <= 2; x <<= 1) {
                    unsigned long long o1 = __shfl_xor_sync(0xffffffffu, k1, x);
                    unsigned long long o2 = __shfl_xor_sync(0xffffffffu, k2, x);
                    unsigned long long n1 = (k1 < o1) ? k1 : o1;
                    unsigned long long mx = (k1 < o1) ? o1 : k1;
                    unsigned long long mn2 = (k2 < o2) ? k2 : o2;
                    k1 = n1;
                    k2 = (mx < mn2) ? mx : mn2;
                }
                if (gc == 0) {
                    size_t base = ((size_t)(m0 + rl) * NGROUPS + group0 + grp) * 2;
                    g_top2[base]     = k1;
                    g_top2[base + 1] = k2;
                }
            }
        }
    }
}

// ---------------- candidate selection + exact rescore ----------------
__global__ void __launch_bounds__(NTHREADS)
vq_candidates(const float* __restrict__ X, const float* __restrict__ W) {
    __shared__ unsigned long long skey[NTHREADS];
    __shared__ int scand[MAXCAND];
    __shared__ int scnt;
    __shared__ unsigned long long sthr;

    int b = blockIdx.x;
    int t = threadIdx.x;
    const unsigned long long* keys = g_top2 + (size_t)b * NGROUPS * 2;

    // per-thread min over 4 keys, then tree-min
    unsigned long long mk = ~0ull;
    unsigned long long my[4];
    #pragma unroll
    for (int i = 0; i < 4; ++i) {
        my[i] = keys[t + i * NTHREADS];
        if (my[i] < mk) mk = my[i];
    }
    skey[t] = mk;
    __syncthreads();
    #pragma unroll
    for (int s = NTHREADS / 2; s > 0; s >>= 1) {
        if (t < s && skey[t + s] < skey[t]) skey[t] = skey[t + s];
        __syncthreads();
    }
    if (t == 0) {
        scnt = 0;
        // threshold in ordered-uint (grid-step) space: coarse min + MARGIN_ULPS steps
        unsigned int mord = (unsigned int)(skey[0] >> 32);
        sthr = ((unsigned long long)(mord + MARGIN_ULPS) << 32) | 0xffffffffull;
    }
    __syncthreads();

    unsigned long long thr = sthr;
    #pragma unroll
    for (int i = 0; i < 4; ++i) {
        if (my[i] <= thr) {
            int pos = atomicAdd(&scnt, 1);
            if (pos < MAXCAND) scand[pos] = (int)(my[i] & 0xffffffffu);
        }
    }
    __syncthreads();
    int n = scnt < MAXCAND ? scnt : MAXCAND;

    // exact rescore: double-accumulated dot, fp32 distance rounding
    const float* xr = X + (size_t)b * DIM_;
    float xn = g_xnorm[b];
    unsigned long long best = ~0ull;
    for (int i = 0; i < n; ++i) {
        int col = scand[i];
        const float* wr = W + (size_t)col * DIM_;
        double s = 0.0;
        for (int k = t; k < DIM_; k += NTHREADS)
            s += (double)xr[k] * (double)wr[k];
        double tot = block_reduce256(s);
        if (t == 0) {
            float d = __fadd_rn(__fadd_rn(xn, g_enorm[col]), -2.0f * (float)tot);
            unsigned long long key = ((unsigned long long)f2ord(d) << 32) | (unsigned)col;
            if (key < best) best = key;
        }
    }
    if (t == 0) g_best[b] = best;
}

// ---------------- histogram ----------------
__global__ void vq_counts() {
    int b = blockIdx.x * blockDim.x + threadIdx.x;
    if (b < B_) {
        int idx = (int)(g_best[b] & 0xffffffffu);
        atomicAdd(&g_counts[idx], 1);
    }
}

// ---------------- quantized output (STE) + loss partials ----------------
__global__ void vq_quant(const float* __restrict__ X, const float* __restrict__ W,
                         float* __restrict__ qout) {
    int b = blockIdx.x;
    int idx = (int)(g_best[b] & 0xffffffffu);
    const float4* xr = (const float4*)(X + (size_t)b * DIM_);
    const float4* qr = (const float4*)(W + (size_t)idx * DIM_);
    float* o = qout + (size_t)b * DIM_;
    double s = 0.0;
    for (int c = threadIdx.x; c < DIM_ / 4; c += blockDim.x) {
        float4 x = xr[c];
        float4 q = qr[c];
        float d0 = __fadd_rn(q.x, -x.x);
        float d1 = __fadd_rn(q.y, -x.y);
        float d2 = __fadd_rn(q.z, -x.z);
        float d3 = __fadd_rn(q.w, -x.w);
        o[4 * c + 0] = __fadd_rn(x.x, d0);
        o[4 * c + 1] = __fadd_rn(x.y, d1);
        o[4 * c + 2] = __fadd_rn(x.z, d2);
        o[4 * c + 3] = __fadd_rn(x.w, d3);
        s += (double)d0 * d0 + (double)d1 * d1 + (double)d2 * d2 + (double)d3 * d3;
    }
    double tot = block_reduce256(s);
    if (threadIdx.x == 0) g_loss_partial[b] = tot;
}

// ---------------- one-hot encodings ----------------
__global__ void vq_encodings(float* __restrict__ enc) {
    long long gid = (long long)blockIdx.x * blockDim.x + threadIdx.x;
    const long long total = (long long)B_ * (E_ / 2);
    if (gid >= total) return;
    int b  = (int)(gid >> 13);
    int c2 = (int)(gid & 8191);
    int idx = (int)(g_best[b] & 0xffffffffu);
    int c = c2 * 2;
    float2 v;
    v.x = (c == idx) ? 1.0f : 0.0f;
    v.y = (c + 1 == idx) ? 1.0f : 0.0f;
    ((float2*)enc)[gid] = v;
}

// ---------------- finalize ----------------
__global__ void vq_finalize(float* __restrict__ out_loss, float* __restrict__ out_perp) {
    int t = threadIdx.x;
    double s = 0.0;
    for (int i = t; i < B_; i += NTHREADS) s += g_loss_partial[i];
    double tot = block_reduce256(s);

    double h = 0.0;
    for (int e = t; e < E_; e += NTHREADS) {
        float p = (float)g_counts[e] * (1.0f / (float)B_);
        float term = p * logf(p + 1e-10f);
        h -= (double)term;
    }
    double H = block_reduce256(h);

    if (t == 0) {
        double m = tot / ((double)B_ * (double)DIM_);
        float mf = (float)m;
        out_loss[0] = __fadd_rn(mf, 0.25f * mf);
        out_perp[0] = expf((float)H);
    }
}

// ---------------- launch ----------------
extern "C" void kernel_launch(void* const* d_in, const int* in_sizes, int n_in,
                              void* d_out, int out_size) {
    const float* X;
    const float* W;
    if (in_sizes[0] == B_ * DIM_) {
        X = (const float*)d_in[0];
        W = (const float*)d_in[1];
    } else {
        X = (const float*)d_in[1];
        W = (const float*)d_in[0];
    }

    float* out = (float*)d_out;
    float* out_loss = out;
    float* out_q    = out + 1;
    float* out_perp = out + 1 + (size_t)B_ * DIM_;
    float* out_enc  = out + 2 + (size_t)B_ * DIM_;

    float* xnorm;  cudaGetSymbolAddress((void**)&xnorm, g_xnorm);
    float* enorm;  cudaGetSymbolAddress((void**)&enorm, g_enorm);
    unsigned short *xb, *wb;
    cudaGetSymbolAddress((void**)&xb, g_Xb);
    cudaGetSymbolAddress((void**)&wb, g_Wb);

    vq_init<<<E_ / NTHREADS, NTHREADS>>>();
    vq_prep<<<B_, NTHREADS>>>(X, xb, xnorm);
    vq_prep<<<E_, NTHREADS>>>(W, wb, enorm);

    cudaFuncSetAttribute(vq_gemm_mma, cudaFuncAttributeMaxDynamicSharedMemorySize, SMEM_TOTAL);
    dim3 grid(B_ / TILE_M, E_ / TILE_N);   // x = M fastest: B tiles reused in L2
    vq_gemm_mma<<<grid, NTHREADS, SMEM_TOTAL>>>(xb, wb);

    vq_candidates<<<B_, NTHREADS>>>(X, W);

    vq_counts<<<B_ / NTHREADS, NTHREADS>>>();
    vq_quant<<<B_, NTHREADS>>>(X, W, out_q);

    long long enc_threads = (long long)B_ * (E_ / 2);
    vq_encodings<<<(unsigned)((enc_threads + NTHREADS - 1) / NTHREADS), NTHREADS>>>(out_enc);

    vq_finalize<<<1, NTHREADS>>>(out_loss, out_perp);
}

// round 8
// speedup vs baseline: 5.3966x; 1.0313x over previous
#include <cuda_runtime.h>
#include <cuda_bf16.h>
#include <math.h>
#include <stdint.h>

// Problem constants
#define B_   4096
#define E_   16384
#define DIM_ 4096
#define NTHREADS 256
#define GTHREADS 512

// GEMM tiling
#define TILE_M 128
#define TILE_N 256
#define KCHUNK 64                // bf16 elems per K chunk = 128 bytes per row
#define NCHUNKS (DIM_ / KCHUNK)  // 64
#define NSTAGES 4

#define NGROUPS (E_ / 32)        // 512 groups of 32 cols per row
#define MARGIN_ULPS 3u           // threshold = coarse min + 3 fp32 grid steps
#define MAXCAND 96

// dynamic smem layout (GEMM)
#define SOFF_EN   0              // 256 floats enorm
#define SOFF_XN   1024           // 128 floats xnorm
#define SOFF_STAGE 2048
#define STAGE_BYTES 49152        // Xb 16K | Wb 32K
#define SMEM_TOTAL (SOFF_STAGE + NSTAGES * STAGE_BYTES)  // 198656

// ---------------- device scratch ----------------
__device__ unsigned short     g_Xb[B_ * DIM_];
__device__ unsigned short     g_Wb[E_ * DIM_];
__device__ unsigned long long g_top2[(size_t)B_ * NGROUPS * 2];   // 32MB
__device__ float              g_xnorm[B_];
__device__ float              g_enorm[E_];
__device__ unsigned long long g_best[B_];
__device__ int                g_counts[E_];
__device__ double             g_loss_partial[B_];

// ---------------- helpers ----------------
__device__ __forceinline__ uint32_t smem_to_u32(const void* p) {
    uint32_t a;
    asm("{ .reg .u64 t; cvta.to.shared.u64 t, %1; cvt.u32.u64 %0, t; }" : "=r"(a) : "l"(p));
    return a;
}

__device__ __forceinline__ void ldsm4(uint32_t* r, uint32_t addr) {
    asm volatile("ldmatrix.sync.aligned.m8n8.x4.shared.b16 {%0,%1,%2,%3}, [%4];"
        : "=r"(r[0]), "=r"(r[1]), "=r"(r[2]), "=r"(r[3]) : "r"(addr));
}

__device__ __forceinline__ void mma_bf16(float* d, const uint32_t* a, const uint32_t* b) {
    asm volatile(
        "mma.sync.aligned.m16n8k16.row.col.f32.bf16.bf16.f32 "
        "{%0,%1,%2,%3}, {%4,%5,%6,%7}, {%8,%9}, {%0,%1,%2,%3};"
        : "+f"(d[0]), "+f"(d[1]), "+f"(d[2]), "+f"(d[3])
        : "r"(a[0]), "r"(a[1]), "r"(a[2]), "r"(a[3]), "r"(b[0]), "r"(b[1]));
}

__device__ __forceinline__ unsigned int f2ord(float f) {
    unsigned int u = __float_as_uint(f);
    return (u & 0x80000000u) ? ~u : (u | 0x80000000u);
}

__device__ double block_reduce256(double v) {
    __shared__ double sm[NTHREADS];
    int t = threadIdx.x;
    __syncthreads();
    sm[t] = v;
    __syncthreads();
    #pragma unroll
    for (int s = NTHREADS / 2; s > 0; s >>= 1) {
        if (t < s) sm[t] += sm[t + s];
        __syncthreads();
    }
    return sm[0];
}

// ---------------- init ----------------
__global__ void vq_init() {
    int t = blockIdx.x * blockDim.x + threadIdx.x;
    if (t < E_) g_counts[t] = 0;
}

// ---------------- fused row norm + bf16 convert ----------------
__global__ void vq_prep(const float* __restrict__ src,
                        unsigned short* __restrict__ dst,
                        float* __restrict__ norm) {
    int r = blockIdx.x;
    const float4* p = (const float4*)(src + (size_t)r * DIM_);
    uint2* o = (uint2*)(dst + (size_t)r * DIM_);
    double s = 0.0;
    #pragma unroll
    for (int i = 0; i < DIM_ / 4 / NTHREADS; ++i) {
        int c = threadIdx.x + i * NTHREADS;
        float4 v = p[c];
        s += (double)v.x * v.x + (double)v.y * v.y
           + (double)v.z * v.z + (double)v.w * v.w;
        uint2 q;
        q.x = (uint32_t)__bfloat16_as_ushort(__float2bfloat16(v.x))
            | ((uint32_t)__bfloat16_as_ushort(__float2bfloat16(v.y)) << 16);
        q.y = (uint32_t)__bfloat16_as_ushort(__float2bfloat16(v.z))
            | ((uint32_t)__bfloat16_as_ushort(__float2bfloat16(v.w)) << 16);
        o[c] = q;
    }
    double tot = block_reduce256(s);
    if (threadIdx.x == 0) norm[r] = (float)tot;
}

// ---------------- coarse HMMA GEMM (128x256 tile, 16 warps) + top-2 ----------------
__global__ void __launch_bounds__(GTHREADS)
vq_gemm_mma(const unsigned short* __restrict__ Xb, const unsigned short* __restrict__ Wb) {
    extern __shared__ char smem[];
    uint32_t sbase = smem_to_u32(smem);
    float* sEn = (float*)(smem + SOFF_EN);
    float* sXn = (float*)(smem + SOFF_XN);

    const int tid  = threadIdx.x;
    const int lane = tid & 31;
    const int wid  = tid >> 5;           // 0..15
    const int m0 = blockIdx.x * TILE_M;
    const int n0 = blockIdx.y * TILE_N;
    const int wm = (wid >> 2) * 32;      // warp m offset: 0/32/64/96
    const int wn = (wid & 3) * 64;       // warp n offset: 0/64/128/192

    if (tid < 256) sEn[tid] = g_enorm[n0 + tid];
    else if (tid < 384) sXn[tid - 256] = g_xnorm[m0 + tid - 256];

    // cp.async one K chunk (Xb 128 rows, Wb 256 rows) into stage c%4
    auto load_chunk = [&](int c) {
        int st = c & (NSTAGES - 1);
        int k0 = c * KCHUNK;
        uint32_t stage = sbase + SOFF_STAGE + st * STAGE_BYTES;
        #pragma unroll
        for (int i = 0; i < 6; ++i) {
            int id = i * GTHREADS + tid;       // 0..3071
            const unsigned short* g;
            uint32_t sd;
            if (id < 1024) {
                int row = id >> 3, c16 = id & 7;
                uint32_t off = (uint32_t)(row * 128 + c16 * 16);
                off ^= ((off >> 3) & 0x70);
                g = Xb + (size_t)(m0 + row) * DIM_ + k0 + c16 * 8;
                sd = stage + off;
            } else {
                int q = id - 1024;             // 0..2047
                int row = q >> 3, c16 = q & 7;
                uint32_t off = (uint32_t)(row * 128 + c16 * 16);
                off ^= ((off >> 3) & 0x70);
                g = Wb + (size_t)(n0 + row) * DIM_ + k0 + c16 * 8;
                sd = stage + 16384 + off;
            }
            asm volatile("cp.async.cg.shared.global [%0], [%1], 16;" :: "r"(sd), "l"(g) : "memory");
        }
        asm volatile("cp.async.commit_group;" ::: "memory");
    };

    load_chunk(0);
    load_chunk(1);
    load_chunk(2);

    float acc[2][8][4];
    #pragma unroll
    for (int i = 0; i < 2; ++i)
        #pragma unroll
        for (int j = 0; j < 8; ++j)
            #pragma unroll
            for (int r = 0; r < 4; ++r) acc[i][j][r] = 0.0f;

    const int aRow  = lane & 15;
    const int aKoff = (lane >> 4) * 16;
    const int bRow  = ((lane >> 4) << 3) + (lane & 7);
    const int bKoff = ((lane >> 3) & 1) * 16;

    for (int c = 0; c < NCHUNKS; ++c) {
        asm volatile("cp.async.wait_group 2;" ::: "memory");
        __syncthreads();

        // prefetch next chunk BEFORE compute so loads overlap the MMA block
        if (c + 3 < NCHUNKS) load_chunk(c + 3);
        else asm volatile("cp.async.commit_group;" ::: "memory");

        int st = c & (NSTAGES - 1);
        uint32_t stg = sbase + SOFF_STAGE + st * STAGE_BYTES;

        #pragma unroll
        for (int s = 0; s < 4; ++s) {
            uint32_t af[2][4], bf[8][2];
            #pragma unroll
            for (int mi = 0; mi < 2; ++mi) {
                uint32_t off = (uint32_t)((wm + mi * 16 + aRow) * 128 + s * 32 + aKoff);
                off ^= ((off >> 3) & 0x70);
                ldsm4(af[mi], stg + off);
            }
            #pragma unroll
            for (int ni2 = 0; ni2 < 4; ++ni2) {
                uint32_t off = (uint32_t)((wn + ni2 * 16 + bRow) * 128 + s * 32 + bKoff);
                off ^= ((off >> 3) & 0x70);
                uint32_t t[4];
                ldsm4(t, stg + 16384 + off);
                bf[2 * ni2][0] = t[0]; bf[2 * ni2][1] = t[1];
                bf[2 * ni2 + 1][0] = t[2]; bf[2 * ni2 + 1][1] = t[3];
            }
            #pragma unroll
            for (int mi = 0; mi < 2; ++mi)
                #pragma unroll
                for (int ni = 0; ni < 8; ++ni)
                    mma_bf16(acc[mi][ni], af[mi], bf[ni]);
        }
    }
    __syncthreads();

    // epilogue: per-row top-2 within each of this warp's two 32-col groups
    const int gr = lane >> 2;           // row in 8-group
    const int gc = lane & 3;
    const int gc2 = gc * 2;
    const int group0 = (n0 + wn) >> 5;  // first global 32-col group id

    #pragma unroll
    for (int mi = 0; mi < 2; ++mi) {
        #pragma unroll
        for (int half = 0; half < 2; ++half) {
            int rl = wm + mi * 16 + gr + half * 8;
            float xn = sXn[rl];
            #pragma unroll
            for (int grp = 0; grp < 2; ++grp) {
                unsigned long long k1 = ~0ull, k2 = ~0ull;
                #pragma unroll
                for (int ni = grp * 4; ni < grp * 4 + 4; ++ni)
                    #pragma unroll
                    for (int j = 0; j < 2; ++j) {
                        int nloc = wn + ni * 8 + gc2 + j;
                        float d = __fadd_rn(__fadd_rn(xn, sEn[nloc]),
                                            __fmul_rn(-2.0f, acc[mi][ni][half * 2 + j]));
                        unsigned long long key =
                            ((unsigned long long)f2ord(d) << 32) | (unsigned)(n0 + nloc);
                        if (key < k1) { k2 = k1; k1 = key; }
                        else if (key < k2) { k2 = key; }
                    }
                // merge top-2 across the 4 lanes holding this row
                #pragma unroll
                for (int x = 1; x <= 2; x <<= 1) {
                    unsigned long long o1 = __shfl_xor_sync(0xffffffffu, k1, x);
                    unsigned long long o2 = __shfl_xor_sync(0xffffffffu, k2, x);
                    unsigned long long n1 = (k1 < o1) ? k1 : o1;
                    unsigned long long mx = (k1 < o1) ? o1 : k1;
                    unsigned long long mn2 = (k2 < o2) ? k2 : o2;
                    k1 = n1;
                    k2 = (mx < mn2) ? mx : mn2;
                }
                if (gc == 0) {
                    size_t base = ((size_t)(m0 + rl) * NGROUPS + group0 + grp) * 2;
                    g_top2[base]     = k1;
                    g_top2[base + 1] = k2;
                }
            }
        }
    }
}

// ---------------- candidate selection + exact rescore ----------------
__global__ void __launch_bounds__(NTHREADS)
vq_candidates(const float* __restrict__ X, const float* __restrict__ W) {
    __shared__ unsigned long long skey[NTHREADS];
    __shared__ int scand[MAXCAND];
    __shared__ int scnt;
    __shared__ unsigned long long sthr;

    int b = blockIdx.x;
    int t = threadIdx.x;
    const unsigned long long* keys = g_top2 + (size_t)b * NGROUPS * 2;

    // per-thread min over 4 keys, then tree-min
    unsigned long long mk = ~0ull;
    unsigned long long my[4];
    #pragma unroll
    for (int i = 0; i < 4; ++i) {
        my[i] = keys[t + i * NTHREADS];
        if (my[i] < mk) mk = my[i];
    }
    skey[t] = mk;
    __syncthreads();
    #pragma unroll
    for (int s = NTHREADS / 2; s > 0; s >>= 1) {
        if (t < s && skey[t + s] < skey[t]) skey[t] = skey[t + s];
        __syncthreads();
    }
    if (t == 0) {
        scnt = 0;
        // threshold in ordered-uint (grid-step) space: coarse min + MARGIN_ULPS steps
        unsigned int mord = (unsigned int)(skey[0] >> 32);
        sthr = ((unsigned long long)(mord + MARGIN_ULPS) << 32) | 0xffffffffull;
    }
    __syncthreads();

    unsigned long long thr = sthr;
    #pragma unroll
    for (int i = 0; i < 4; ++i) {
        if (my[i] <= thr) {
            int pos = atomicAdd(&scnt, 1);
            if (pos < MAXCAND) scand[pos] = (int)(my[i] & 0xffffffffu);
        }
    }
    __syncthreads();
    int n = scnt < MAXCAND ? scnt : MAXCAND;

    // exact rescore: double-accumulated dot, fp32 distance rounding
    const float* xr = X + (size_t)b * DIM_;
    float xn = g_xnorm[b];
    unsigned long long best = ~0ull;
    for (int i = 0; i < n; ++i) {
        int col = scand[i];
        const float* wr = W + (size_t)col * DIM_;
        double s = 0.0;
        for (int k = t; k < DIM_; k += NTHREADS)
            s += (double)xr[k] * (double)wr[k];
        double tot = block_reduce256(s);
        if (t == 0) {
            float d = __fadd_rn(__fadd_rn(xn, g_enorm[col]), -2.0f * (float)tot);
            unsigned long long key = ((unsigned long long)f2ord(d) << 32) | (unsigned)col;
            if (key < best) best = key;
        }
    }
    if (t == 0) g_best[b] = best;
}

// ---------------- histogram ----------------
__global__ void vq_counts() {
    int b = blockIdx.x * blockDim.x + threadIdx.x;
    if (b < B_) {
        int idx = (int)(g_best[b] & 0xffffffffu);
        atomicAdd(&g_counts[idx], 1);
    }
}

// ---------------- quantized output (STE) + loss partials ----------------
__global__ void vq_quant(const float* __restrict__ X, const float* __restrict__ W,
                         float* __restrict__ qout) {
    int b = blockIdx.x;
    int idx = (int)(g_best[b] & 0xffffffffu);
    const float4* xr = (const float4*)(X + (size_t)b * DIM_);
    const float4* qr = (const float4*)(W + (size_t)idx * DIM_);
    float* o = qout + (size_t)b * DIM_;
    double s = 0.0;
    for (int c = threadIdx.x; c < DIM_ / 4; c += blockDim.x) {
        float4 x = xr[c];
        float4 q = qr[c];
        float d0 = __fadd_rn(q.x, -x.x);
        float d1 = __fadd_rn(q.y, -x.y);
        float d2 = __fadd_rn(q.z, -x.z);
        float d3 = __fadd_rn(q.w, -x.w);
        o[4 * c + 0] = __fadd_rn(x.x, d0);
        o[4 * c + 1] = __fadd_rn(x.y, d1);
        o[4 * c + 2] = __fadd_rn(x.z, d2);
        o[4 * c + 3] = __fadd_rn(x.w, d3);
        s += (double)d0 * d0 + (double)d1 * d1 + (double)d2 * d2 + (double)d3 * d3;
    }
    double tot = block_reduce256(s);
    if (threadIdx.x == 0) g_loss_partial[b] = tot;
}

// ---------------- one-hot encodings ----------------
__global__ void vq_encodings(float* __restrict__ enc) {
    long long gid = (long long)blockIdx.x * blockDim.x + threadIdx.x;
    const long long total = (long long)B_ * (E_ / 2);
    if (gid >= total) return;
    int b  = (int)(gid >> 13);
    int c2 = (int)(gid & 8191);
    int idx = (int)(g_best[b] & 0xffffffffu);
    int c = c2 * 2;
    float2 v;
    v.x = (c == idx) ? 1.0f : 0.0f;
    v.y = (c + 1 == idx) ? 1.0f : 0.0f;
    ((float2*)enc)[gid] = v;
}

// ---------------- finalize ----------------
__global__ void vq_finalize(float* __restrict__ out_loss, float* __restrict__ out_perp) {
    int t = threadIdx.x;
    double s = 0.0;
    for (int i = t; i < B_; i += NTHREADS) s += g_loss_partial[i];
    double tot = block_reduce256(s);

    double h = 0.0;
    for (int e = t; e < E_; e += NTHREADS) {
        float p = (float)g_counts[e] * (1.0f / (float)B_);
        float term = p * logf(p + 1e-10f);
        h -= (double)term;
    }
    double H = block_reduce256(h);

    if (t == 0) {
        double m = tot / ((double)B_ * (double)DIM_);
        float mf = (float)m;
        out_loss[0] = __fadd_rn(mf, 0.25f * mf);
        out_perp[0] = expf((float)H);
    }
}

// ---------------- launch ----------------
extern "C" void kernel_launch(void* const* d_in, const int* in_sizes, int n_in,
                              void* d_out, int out_size) {
    const float* X;
    const float* W;
    if (in_sizes[0] == B_ * DIM_) {
        X = (const float*)d_in[0];
        W = (const float*)d_in[1];
    } else {
        X = (const float*)d_in[1];
        W = (const float*)d_in[0];
    }

    float* out = (float*)d_out;
    float* out_loss = out;
    float* out_q    = out + 1;
    float* out_perp = out + 1 + (size_t)B_ * DIM_;
    float* out_enc  = out + 2 + (size_t)B_ * DIM_;

    float* xnorm;  cudaGetSymbolAddress((void**)&xnorm, g_xnorm);
    float* enorm;  cudaGetSymbolAddress((void**)&enorm, g_enorm);
    unsigned short *xb, *wb;
    cudaGetSymbolAddress((void**)&xb, g_Xb);
    cudaGetSymbolAddress((void**)&wb, g_Wb);

    vq_init<<<E_ / NTHREADS, NTHREADS>>>();
    vq_prep<<<B_, NTHREADS>>>(X, xb, xnorm);
    vq_prep<<<E_, NTHREADS>>>(W, wb, enorm);

    cudaFuncSetAttribute(vq_gemm_mma, cudaFuncAttributeMaxDynamicSharedMemorySize, SMEM_TOTAL);
    dim3 grid(B_ / TILE_M, E_ / TILE_N);   // x = M fastest: B tiles reused in L2
    vq_gemm_mma<<<grid, GTHREADS, SMEM_TOTAL>>>(xb, wb);

    vq_candidates<<<B_, NTHREADS>>>(X, W);

    vq_counts<<<B_ / NTHREADS, NTHREADS>>>();
    vq_quant<<<B_, NTHREADS>>>(X, W, out_q);

    long long enc_threads = (long long)B_ * (E_ / 2);
    vq_encodings<<<(unsigned)((enc_threads + NTHREADS - 1) / NTHREADS), NTHREADS>>>(out_enc);

    vq_finalize<<<1, NTHREADS>>>(out_loss, out_perp);
}